// round 1
// baseline (speedup 1.0000x reference)
#include <cuda_runtime.h>
#include <cstdint>

#define BATCH 16
#define H 1024
#define W 1024
#define PLANE (H * W)

// 64 MB scratch for intermediate T_new (advection result) — static device
// global, allowed under the allocation guards.
__device__ float g_Tmid[BATCH * PLANE];
__device__ unsigned int g_umax_bits;

__device__ __forceinline__ float compute_dt() {
    const float dx = (float)(1.0 / 126.0);
    float uv_mag = __uint_as_float(g_umax_bits);
    float dt_advect = 0.5f * 0.1f * dx / uv_mag;
    float dx2 = dx * dx;
    float dt_diffuse = 0.5f * (dx2 * dx2) / (dx2 + dx2);
    return fminf(dt_advect, dt_diffuse);
}

__global__ void k_init() { g_umax_bits = 0u; }

// Max |.| over channels 0 (u) and 1 (v) of every batch: 32M floats.
__global__ void k_reduce(const float* __restrict__ in) {
    const long long total_vec = (long long)BATCH * 2 * PLANE / 4;
    float m = 0.0f;
    for (long long i = (long long)blockIdx.x * blockDim.x + threadIdx.x;
         i < total_vec;
         i += (long long)gridDim.x * blockDim.x) {
        long long e = i * 4;
        int b = (int)(e / (2LL * PLANE));
        int r = (int)(e % (2LL * PLANE));
        // channels 0,1 are the first 2 contiguous planes of each batch
        const float4 v4 = *(const float4*)(in + (long long)b * 4 * PLANE + r);
        m = fmaxf(m, fmaxf(fmaxf(fabsf(v4.x), fabsf(v4.y)),
                           fmaxf(fabsf(v4.z), fabsf(v4.w))));
    }
    #pragma unroll
    for (int o = 16; o > 0; o >>= 1)
        m = fmaxf(m, __shfl_xor_sync(0xffffffffu, m, o));
    __shared__ float sm[32];
    int lane = threadIdx.x & 31, w = threadIdx.x >> 5;
    if (lane == 0) sm[w] = m;
    __syncthreads();
    if (w == 0) {
        m = (lane < (int)(blockDim.x >> 5)) ? sm[lane] : 0.0f;
        #pragma unroll
        for (int o = 16; o > 0; o >>= 1)
            m = fmaxf(m, __shfl_xor_sync(0xffffffffu, m, o));
        if (lane == 0)
            atomicMax(&g_umax_bits, __float_as_uint(m));  // m >= 0: uint order == float order
    }
}

// T_mid = T_prev + dt * (-u*dT_dx - v*dT_dy), upwind gradients, replicate pad.
__global__ void k_advect(const float* __restrict__ in) {
    int x = blockIdx.x * blockDim.x + threadIdx.x;
    int y = blockIdx.y;
    int b = blockIdx.z;
    if (x >= W) return;

    const float dx = (float)(1.0 / 126.0);
    const float dt = compute_dt();

    const float* base = in + (size_t)b * 4 * PLANE;
    const float* U = base;
    const float* V = base + PLANE;
    const float* T = base + 2 * PLANE;

    int idx = y * W + x;
    float c = __ldg(T + idx);
    float l = (x > 0)     ? __ldg(T + idx - 1) : c;
    float r = (x < W - 1) ? __ldg(T + idx + 1) : c;
    float t = (y > 0)     ? __ldg(T + idx - W) : c;
    float d = (y < H - 1) ? __ldg(T + idx + W) : c;
    float u = __ldg(U + idx);
    float v = __ldg(V + idx);

    float gx = (u > 0.0f) ? (c - l) / dx : ((u < 0.0f) ? (r - c) / dx : 0.0f);
    float gy = (v > 0.0f) ? (c - t) / dx : ((v < 0.0f) ? (d - c) / dx : 0.0f);

    g_Tmid[(size_t)b * PLANE + idx] = c + dt * (-u * gx - v * gy);
}

// out = T_mid + dt * (lap(T_mid) + RaQ), 3x3 weighted laplacian, replicate pad.
__global__ void k_lap(const float* __restrict__ in, float* __restrict__ out,
                      int out_size) {
    int x = blockIdx.x * blockDim.x + threadIdx.x;
    int y = blockIdx.y;
    int b = blockIdx.z;
    if (x >= W) return;

    const float dx = (float)(1.0 / 126.0);
    const float dt = compute_dt();

    const float* R = in + (size_t)b * 4 * PLANE + 3 * PLANE;
    const float* T = g_Tmid + (size_t)b * PLANE;

    int xm = max(x - 1, 0), xp = min(x + 1, W - 1);
    int ym = max(y - 1, 0), yp = min(y + 1, H - 1);

    float t00 = T[ym * W + xm], t01 = T[ym * W + x], t02 = T[ym * W + xp];
    float t10 = T[y  * W + xm], t11 = T[y  * W + x], t12 = T[y  * W + xp];
    float t20 = T[yp * W + xm], t21 = T[yp * W + x], t22 = T[yp * W + xp];

    float lap = 0.25f * (t00 + 2.0f * t01 + t02 +
                         2.0f * t10 - 12.0f * t11 + 2.0f * t12 +
                         t20 + 2.0f * t21 + t22) / (dx * dx);

    int idx = y * W + x;
    out[(size_t)b * PLANE + idx] = t11 + dt * (lap + __ldg(R + idx));

    // scalar dt is the second output, appended after T_new
    if (b == 0 && y == 0 && x == 0 && out_size > BATCH * PLANE)
        out[BATCH * PLANE] = dt;
}

extern "C" void kernel_launch(void* const* d_in, const int* in_sizes, int n_in,
                              void* d_out, int out_size) {
    const float* in = (const float*)d_in[0];
    float* out = (float*)d_out;
    (void)in_sizes; (void)n_in;

    k_init<<<1, 1>>>();

    k_reduce<<<1184, 256>>>(in);

    dim3 blk(256, 1, 1);
    dim3 grd(W / 256, H, BATCH);
    k_advect<<<grd, blk>>>(in);
    k_lap<<<grd, blk>>>(in, out, out_size);
}

// round 3
// speedup vs baseline: 1.2723x; 1.2723x over previous
#include <cuda_runtime.h>
#include <cstdint>

#define BATCH 16
#define H 1024
#define W 1024
#define PLANE (H * W)

// Tile geometry for the fused kernel
#define TX 128
#define TY 32
#define ST_W (TX + 4)   // 132 — T_prev staging (halo 2)
#define ST_H (TY + 4)   // 36
#define SM_W (TX + 2)   // 130 — T_mid staging (halo 1)
#define SM_H (TY + 2)   // 34

__device__ unsigned int g_umax_bits;

#define DXF ((float)(1.0 / 126.0))

__device__ __forceinline__ float compute_dt() {
    float uv_mag = __uint_as_float(g_umax_bits);
    float dt_advect = 0.5f * 0.1f * DXF / uv_mag;
    float dx2 = DXF * DXF;
    float dt_diffuse = 0.5f * (dx2 * dx2) / (dx2 + dx2);
    return fminf(dt_advect, dt_diffuse);
}

__global__ void k_init() { g_umax_bits = 0u; }

// Max |.| over channels 0 (u) and 1 (v) of every batch: 32M floats.
__global__ void k_reduce(const float* __restrict__ in) {
    const int total_vec = BATCH * 2 * PLANE / 4;  // 8M float4
    float m = 0.0f;
    for (int i = blockIdx.x * blockDim.x + threadIdx.x;
         i < total_vec;
         i += gridDim.x * blockDim.x) {
        int b = i >> 19;                 // 2*PLANE/4 = 2^19
        int r = i & ((1 << 19) - 1);
        const float4 v4 = ((const float4*)(in + (size_t)b * 4 * PLANE))[r];
        m = fmaxf(m, fmaxf(fmaxf(fabsf(v4.x), fabsf(v4.y)),
                           fmaxf(fabsf(v4.z), fabsf(v4.w))));
    }
    #pragma unroll
    for (int o = 16; o > 0; o >>= 1)
        m = fmaxf(m, __shfl_xor_sync(0xffffffffu, m, o));
    __shared__ float sm[32];
    int lane = threadIdx.x & 31, w = threadIdx.x >> 5;
    if (lane == 0) sm[w] = m;
    __syncthreads();
    if (w == 0) {
        m = (lane < (int)(blockDim.x >> 5)) ? sm[lane] : 0.0f;
        #pragma unroll
        for (int o = 16; o > 0; o >>= 1)
            m = fmaxf(m, __shfl_xor_sync(0xffffffffu, m, o));
        if (lane == 0)
            atomicMax(&g_umax_bits, __float_as_uint(m));  // m >= 0: bit order == value order
    }
}

// Fused: advect (upwind) then 3x3 laplacian, all through shared memory.
// Replicate padding realized via index clamping.
__global__ __launch_bounds__(256) void k_fused(const float* __restrict__ in,
                                               float* __restrict__ out,
                                               int out_size) {
    __shared__ float sT[ST_H][ST_W];   // T_prev tile, halo 2
    __shared__ float sM[SM_H][SM_W];   // T_mid tile, halo 1

    const int ox0 = blockIdx.x * TX;
    const int oy0 = blockIdx.y * TY;
    const int b   = blockIdx.z;
    const int gx0 = ox0 - 2;
    const int gy0 = oy0 - 2;
    const int tid = threadIdx.x;

    const float* base = in + (size_t)b * 4 * PLANE;
    const float* U = base;
    const float* V = base + PLANE;
    const float* T = base + 2 * PLANE;
    const float* R = base + 3 * PLANE;

    const float rdx = 1.0f / DXF;
    const float dt = compute_dt();

    // Stage 1: T_prev -> sT (clamped coords)
    for (int l = tid; l < ST_H * ST_W; l += 256) {
        int sy = l / ST_W, sx = l - sy * ST_W;
        int py = min(max(gy0 + sy, 0), H - 1);
        int px = min(max(gx0 + sx, 0), W - 1);
        sT[sy][sx] = __ldg(T + py * W + px);
    }
    __syncthreads();

    // Stage 2: compute T_mid on tile+halo1 -> sM.
    // sM slot m holds T_mid(clamp(gm)) where gm = (gy0+1+my, gx0+1+mx).
    // sT slot q-gy0 holds T_prev(q) for any real coordinate q in range.
    for (int l = tid; l < SM_H * SM_W; l += 256) {
        int my = l / SM_W, mx = l - my * SM_W;
        int py = min(max(gy0 + 1 + my, 0), H - 1);
        int px = min(max(gx0 + 1 + mx, 0), W - 1);

        int syc = py - gy0;
        int sxc = px - gx0;
        int sym = max(py - 1, 0) - gy0;
        int syp = min(py + 1, H - 1) - gy0;
        int sxm = max(px - 1, 0) - gx0;
        int sxp = min(px + 1, W - 1) - gx0;

        float c   = sT[syc][sxc];
        float lft = sT[syc][sxm];
        float rgt = sT[syc][sxp];
        float top = sT[sym][sxc];
        float bot = sT[syp][sxc];

        int gidx = py * W + px;
        float u = __ldg(U + gidx);
        float v = __ldg(V + gidx);

        float gx = (u > 0.0f) ? (c - lft) * rdx
                 : ((u < 0.0f) ? (rgt - c) * rdx : 0.0f);
        float gy = (v > 0.0f) ? (c - top) * rdx
                 : ((v < 0.0f) ? (bot - c) * rdx : 0.0f);

        sM[my][mx] = c + dt * (-u * gx - v * gy);
    }
    __syncthreads();

    // Stage 3: laplacian from sM, add RaQ, write output tile.
    const float lapc = 0.25f * rdx * rdx;
    for (int l = tid; l < TX * TY; l += 256) {
        int ty = l >> 7, tx = l & (TX - 1);
        int oy = oy0 + ty, ox = ox0 + tx;

        int m1 = oy - gy0 - 1;
        int m0 = max(oy - 1, 0) - gy0 - 1;
        int m2 = min(oy + 1, H - 1) - gy0 - 1;
        int n1 = ox - gx0 - 1;
        int n0 = max(ox - 1, 0) - gx0 - 1;
        int n2 = min(ox + 1, W - 1) - gx0 - 1;

        float t00 = sM[m0][n0], t01 = sM[m0][n1], t02 = sM[m0][n2];
        float t10 = sM[m1][n0], t11 = sM[m1][n1], t12 = sM[m1][n2];
        float t20 = sM[m2][n0], t21 = sM[m2][n1], t22 = sM[m2][n2];

        float lap = lapc * (t00 + 2.0f * t01 + t02 +
                            2.0f * t10 - 12.0f * t11 + 2.0f * t12 +
                            t20 + 2.0f * t21 + t22);

        int gidx = oy * W + ox;
        out[(size_t)b * PLANE + gidx] = t11 + dt * (lap + __ldg(R + gidx));
    }

    // Scalar dt is the second output element after T_new.
    if (blockIdx.x == 0 && blockIdx.y == 0 && b == 0 && tid == 0 &&
        out_size > BATCH * PLANE)
        out[BATCH * PLANE] = dt;
}

extern "C" void kernel_launch(void* const* d_in, const int* in_sizes, int n_in,
                              void* d_out, int out_size) {
    const float* in = (const float*)d_in[0];
    float* out = (float*)d_out;
    (void)in_sizes; (void)n_in;

    k_init<<<1, 1>>>();
    k_reduce<<<1184, 256>>>(in);

    dim3 grd(W / TX, H / TY, BATCH);
    k_fused<<<grd, 256>>>(in, out, out_size);
}

// round 6
// speedup vs baseline: 1.4927x; 1.1732x over previous
#include <cuda_runtime.h>
#include <cstdint>

#define BATCH 16
#define H 1024
#define W 1024
#define PLANE (H * W)

#define TX 128
#define TY 32
#define ST_W (TX + 8)   // 136 floats, x base = ox0-4 (16B aligned)
#define ST_H (TY + 4)   // 36
#define SM_W (TX + 2)   // 130
#define SM_H (TY + 2)   // 34

#define NRED 592        // reduce blocks (4 waves of 148)

#define DXF ((float)(1.0 / 126.0))

__device__ float g_partial[NRED];

// ---------------------------------------------------------------------------
// Stage A: per-block max |u|,|v| partials (no atomics, no init kernel).
// ---------------------------------------------------------------------------
__global__ __launch_bounds__(256) void k_reduce(const float* __restrict__ in) {
    const int total_vec = BATCH * 2 * PLANE / 4;  // 8M float4
    float m = 0.0f;
    for (int i = blockIdx.x * blockDim.x + threadIdx.x;
         i < total_vec;
         i += gridDim.x * blockDim.x) {
        int b = i >> 19;                  // 2*PLANE/4 = 2^19
        int r = i & ((1 << 19) - 1);
        const float4 v4 = ((const float4*)(in + (size_t)b * 4 * PLANE))[r];
        m = fmaxf(m, fmaxf(fmaxf(fabsf(v4.x), fabsf(v4.y)),
                           fmaxf(fabsf(v4.z), fabsf(v4.w))));
    }
    #pragma unroll
    for (int o = 16; o > 0; o >>= 1)
        m = fmaxf(m, __shfl_xor_sync(0xffffffffu, m, o));
    __shared__ float sm[8];
    int lane = threadIdx.x & 31, w = threadIdx.x >> 5;
    if (lane == 0) sm[w] = m;
    __syncthreads();
    if (w == 0) {
        m = (lane < 8) ? sm[lane] : 0.0f;
        #pragma unroll
        for (int o = 4; o > 0; o >>= 1)
            m = fmaxf(m, __shfl_xor_sync(0xffffffffu, m, o));
        if (lane == 0) g_partial[blockIdx.x] = m;
    }
}

// ---------------------------------------------------------------------------
// Stage B: fused advect + laplacian.
//  - stage 1: T_prev -> sT (float4 fast path for interior blocks)
//  - stage 2: upwind advection -> sM (halo 1)
//  - stage 3: separable 3x3 laplacian via per-column register rotation
// Clamping happens ONLY when building sT (and u/v addresses at boundaries);
// stages 2/3 index smem unclamped — replicated slots already hold edge values.
// ---------------------------------------------------------------------------
__global__ __launch_bounds__(256) void k_fused(const float* __restrict__ in,
                                               float* __restrict__ out,
                                               int out_size) {
    __shared__ float sT[ST_H][ST_W];
    __shared__ float sM[SM_H][SM_W];
    __shared__ float s_dt;

    const int bx = blockIdx.x, by = blockIdx.y, b = blockIdx.z;
    const int ox0 = bx * TX, oy0 = by * TY;
    const int gy0 = oy0 - 2;
    const int xbase = ox0 - 4;
    const int tid = threadIdx.x;
    const bool interior = (bx > 0) & (bx < W / TX - 1) &
                          (by > 0) & (by < H / TY - 1);

    const float* base = in + (size_t)b * 4 * PLANE;
    const float* U = base;
    const float* V = base + PLANE;
    const float* T = base + 2 * PLANE;
    const float* R = base + 3 * PLANE;

    // dt prologue on warp 0 — overlaps with stage-1 staging of other warps.
    if (tid < 32) {
        float m = 0.0f;
        for (int i = tid; i < NRED; i += 32) m = fmaxf(m, g_partial[i]);
        #pragma unroll
        for (int o = 16; o > 0; o >>= 1)
            m = fmaxf(m, __shfl_xor_sync(0xffffffffu, m, o));
        if (tid == 0) {
            float dt_a = 0.5f * 0.1f * DXF / m;
            float dx2 = DXF * DXF;
            float dt_d = 0.5f * (dx2 * dx2) / (dx2 + dx2);
            s_dt = fminf(dt_a, dt_d);
        }
    }

    // ---- stage 1: T_prev -> sT ----
    if (interior) {
        for (int l = tid; l < ST_H * (ST_W / 4); l += 256) {
            int sy = l / (ST_W / 4), sx4 = l - sy * (ST_W / 4);
            ((float4*)&sT[sy][0])[sx4] =
                *(const float4*)(T + (gy0 + sy) * W + xbase + sx4 * 4);
        }
    } else {
        for (int l = tid; l < ST_H * ST_W; l += 256) {
            int sy = l / ST_W, sx = l - sy * ST_W;
            int py = min(max(gy0 + sy, 0), H - 1);
            int px = min(max(xbase + sx, 0), W - 1);
            sT[sy][sx] = __ldg(T + py * W + px);
        }
    }
    __syncthreads();

    const float dt = s_dt;
    const float rdx = 1.0f / DXF;

    // ---- stage 2: advect -> sM (slot (my,mx) = T_mid(clamp(oy0-1+my, ox0-1+mx))) ----
    if (interior) {
        for (int l = tid; l < SM_H * SM_W; l += 256) {
            int my = l / SM_W, mx = l - my * SM_W;
            int py = gy0 + 1 + my, px = ox0 - 1 + mx;
            float c   = sT[my + 1][mx + 3];
            float lft = sT[my + 1][mx + 2];
            float rgt = sT[my + 1][mx + 4];
            float top = sT[my][mx + 3];
            float bot = sT[my + 2][mx + 3];
            int gidx = py * W + px;
            float u = __ldg(U + gidx);
            float v = __ldg(V + gidx);
            float gx = (u > 0.0f) ? (c - lft) * rdx
                     : ((u < 0.0f) ? (rgt - c) * rdx : 0.0f);
            float gy = (v > 0.0f) ? (c - top) * rdx
                     : ((v < 0.0f) ? (bot - c) * rdx : 0.0f);
            sM[my][mx] = c + dt * (-u * gx - v * gy);
        }
    } else {
        for (int l = tid; l < SM_H * SM_W; l += 256) {
            int my = l / SM_W, mx = l - my * SM_W;
            int py = min(max(gy0 + 1 + my, 0), H - 1);
            int px = min(max(ox0 - 1 + mx, 0), W - 1);
            int sy = py - gy0;      // clamped center slot; +/-1 slots hold
            int sx = px - xbase;    // clamp(py+-1)/clamp(px+-1) automatically
            float c   = sT[sy][sx];
            float lft = sT[sy][sx - 1];
            float rgt = sT[sy][sx + 1];
            float top = sT[sy - 1][sx];
            float bot = sT[sy + 1][sx];
            int gidx = py * W + px;
            float u = __ldg(U + gidx);
            float v = __ldg(V + gidx);
            float gx = (u > 0.0f) ? (c - lft) * rdx
                     : ((u < 0.0f) ? (rgt - c) * rdx : 0.0f);
            float gy = (v > 0.0f) ? (c - top) * rdx
                     : ((v < 0.0f) ? (bot - c) * rdx : 0.0f);
            sM[my][mx] = c + dt * (-u * gx - v * gy);
        }
    }
    __syncthreads();

    // ---- stage 3: separable laplacian, register rotation, no clamps ----
    {
        const int tx = tid & 127;
        const int y0 = (tid >> 7) * (TY / 2);   // 0 or 16
        const float lapc = 0.25f * rdx * rdx;
        const float c4 = 4.0f * rdx * rdx;

        float a0 = sM[y0][tx], a1 = sM[y0][tx + 1], a2 = sM[y0][tx + 2];
        float hb0 = a0 + 2.0f * a1 + a2;
        float b0 = sM[y0 + 1][tx], b1 = sM[y0 + 1][tx + 1], b2 = sM[y0 + 1][tx + 2];
        float hb1 = b0 + 2.0f * b1 + b2;
        float cc = b1;

        const int ox = ox0 + tx;
        size_t obase = (size_t)b * PLANE + (size_t)(oy0 + y0) * W + ox;
        const float* Rp = R + (oy0 + y0) * W + ox;

        #pragma unroll 4
        for (int r2 = 0; r2 < TY / 2; ++r2) {
            int j = y0 + 2 + r2;
            float d0 = sM[j][tx], d1 = sM[j][tx + 1], d2 = sM[j][tx + 2];
            float hb2 = d0 + 2.0f * d1 + d2;
            // 0.25*(v-blur of h-blur) - 4*center  ==  reference 3x3 weights
            float lap = lapc * (hb0 + 2.0f * hb1 + hb2) - c4 * cc;
            out[obase] = cc + dt * (lap + __ldg(Rp));
            hb0 = hb1; hb1 = hb2; cc = d1;
            obase += W; Rp += W;
        }
    }

    // scalar dt — second output element
    if (bx == 0 && by == 0 && b == 0 && tid == 0 && out_size > BATCH * PLANE)
        out[BATCH * PLANE] = dt;
}

extern "C" void kernel_launch(void* const* d_in, const int* in_sizes, int n_in,
                              void* d_out, int out_size) {
    const float* in = (const float*)d_in[0];
    float* out = (float*)d_out;
    (void)in_sizes; (void)n_in;

    k_reduce<<<NRED, 256>>>(in);

    dim3 grd(W / TX, H / TY, BATCH);
    k_fused<<<grd, 256>>>(in, out, out_size);
}

// round 8
// speedup vs baseline: 1.6319x; 1.0933x over previous
#include <cuda_runtime.h>
#include <cstdint>

#define BATCH 16
#define H 1024
#define W 1024
#define PLANE (H * W)

#define TX 128
#define TY 16
#define ST_W (TX + 8)   // 136 floats, x base = ox0-4 (16B aligned)
#define ST_H (TY + 4)   // 20 rows, y base = oy0-2
#define SU_H (TY + 2)   // 18 rows, y base = oy0-1
#define SM_W (TX + 2)   // 130
#define SM_H (TY + 2)   // 18

#define NRED 296
#define RED_STRIDE (NRED * 512)

#define DXF ((float)(1.0 / 126.0))

__device__ float g_partial[NRED];

__device__ __forceinline__ void cpa16(uint32_t dst, const float* src) {
    asm volatile("cp.async.cg.shared.global [%0], [%1], 16;\n"
                 :: "r"(dst), "l"(src));
}
__device__ __forceinline__ void cpa_commit_wait() {
    asm volatile("cp.async.commit_group;\n");
    asm volatile("cp.async.wait_group 0;\n");
}

// ---------------------------------------------------------------------------
// Stage A: per-block max |u|,|v| partials. Unroll-4 independent accumulators.
// ---------------------------------------------------------------------------
__global__ __launch_bounds__(512) void k_reduce(const float* __restrict__ in) {
    const int total_vec = BATCH * 2 * PLANE / 4;  // 8388608 float4
    const float4* in4 = (const float4*)in;

    float m0 = 0.f, m1 = 0.f, m2 = 0.f, m3 = 0.f;
    int i = blockIdx.x * 512 + threadIdx.x;

    // float4 index within full tensor: i + (i & ~(2^19-1))  (skips planes 2,3)
    #define RED_IDX(j) ((j) + ((j) & ~((1 << 19) - 1)))
    for (; i + 3 * RED_STRIDE < total_vec; i += 4 * RED_STRIDE) {
        float4 a = in4[RED_IDX(i)];
        float4 b = in4[RED_IDX(i + RED_STRIDE)];
        float4 c = in4[RED_IDX(i + 2 * RED_STRIDE)];
        float4 d = in4[RED_IDX(i + 3 * RED_STRIDE)];
        m0 = fmaxf(m0, fmaxf(fmaxf(fabsf(a.x), fabsf(a.y)), fmaxf(fabsf(a.z), fabsf(a.w))));
        m1 = fmaxf(m1, fmaxf(fmaxf(fabsf(b.x), fabsf(b.y)), fmaxf(fabsf(b.z), fabsf(b.w))));
        m2 = fmaxf(m2, fmaxf(fmaxf(fabsf(c.x), fabsf(c.y)), fmaxf(fabsf(c.z), fabsf(c.w))));
        m3 = fmaxf(m3, fmaxf(fmaxf(fabsf(d.x), fabsf(d.y)), fmaxf(fabsf(d.z), fabsf(d.w))));
    }
    for (; i < total_vec; i += RED_STRIDE) {
        float4 a = in4[RED_IDX(i)];
        m0 = fmaxf(m0, fmaxf(fmaxf(fabsf(a.x), fabsf(a.y)), fmaxf(fabsf(a.z), fabsf(a.w))));
    }
    float m = fmaxf(fmaxf(m0, m1), fmaxf(m2, m3));

    #pragma unroll
    for (int o = 16; o > 0; o >>= 1)
        m = fmaxf(m, __shfl_xor_sync(0xffffffffu, m, o));
    __shared__ float sm[16];
    int lane = threadIdx.x & 31, w = threadIdx.x >> 5;
    if (lane == 0) sm[w] = m;
    __syncthreads();
    if (w == 0) {
        m = (lane < 16) ? sm[lane] : 0.0f;
        #pragma unroll
        for (int o = 8; o > 0; o >>= 1)
            m = fmaxf(m, __shfl_xor_sync(0xffffffffu, m, o));
        if (lane == 0) g_partial[blockIdx.x] = m;
    }
}

// ---------------------------------------------------------------------------
// Stage B: fused advect + laplacian. All global reads front-loaded:
//   - R prefetched into registers (4/thread)
//   - T, u, v staged via cp.async into smem
// Stage 2 is pure LDS+FMA; stage 3 is separable laplacian w/ register rotation.
// ---------------------------------------------------------------------------
__global__ __launch_bounds__(512, 3) void k_fused(const float* __restrict__ in,
                                                  float* __restrict__ out,
                                                  int out_size) {
    __shared__ float sT[ST_H][ST_W];
    __shared__ float sU[SU_H][ST_W];
    __shared__ float sV[SU_H][ST_W];
    __shared__ float sM[SM_H][SM_W];
    __shared__ float s_dt;

    const int bx = blockIdx.x, by = blockIdx.y, b = blockIdx.z;
    const int ox0 = bx * TX, oy0 = by * TY;
    const int gy0 = oy0 - 2;
    const int xbase = ox0 - 4;
    const int tid = threadIdx.x;
    const bool interior = (bx > 0) & (bx < W / TX - 1) &
                          (by > 0) & (by < H / TY - 1);

    const float* base = in + (size_t)b * 4 * PLANE;
    const float* U = base;
    const float* V = base + PLANE;
    const float* T = base + 2 * PLANE;
    const float* R = base + 3 * PLANE;

    // R prefetch: 4 output rows per thread, issued first.
    const int tx3 = tid & 127;
    const int y0 = (tid >> 7) * 4;
    const int ox = ox0 + tx3;
    float Rpre[4];
    #pragma unroll
    for (int r2 = 0; r2 < 4; ++r2)
        Rpre[r2] = __ldg(R + (oy0 + y0 + r2) * W + ox);

    // dt prologue on warp 0 (overlaps with staging by other warps).
    if (tid < 32) {
        float m = 0.0f;
        for (int i = tid; i < NRED; i += 32) m = fmaxf(m, g_partial[i]);
        #pragma unroll
        for (int o = 16; o > 0; o >>= 1)
            m = fmaxf(m, __shfl_xor_sync(0xffffffffu, m, o));
        if (tid == 0) {
            float dt_a = 0.5f * 0.1f * DXF / m;
            float dx2 = DXF * DXF;
            float dt_d = 0.5f * (dx2 * dx2) / (dx2 + dx2);
            s_dt = fminf(dt_a, dt_d);
        }
    }

    // ---- stage 1: stage T, u, v into smem ----
    if (interior) {
        // 16B async chunks: sT 20x34, sU 18x34, sV 18x34
        const int NT = ST_H * (ST_W / 4);              // 680
        const int NU = SU_H * (ST_W / 4);              // 612
        for (int l = tid; l < NT + 2 * NU; l += 512) {
            if (l < NT) {
                int ro = l / 34, c = l - ro * 34;
                cpa16((uint32_t)__cvta_generic_to_shared(&sT[ro][c * 4]),
                      T + (gy0 + ro) * W + xbase + c * 4);
            } else if (l < NT + NU) {
                int li = l - NT;
                int ro = li / 34, c = li - ro * 34;
                cpa16((uint32_t)__cvta_generic_to_shared(&sU[ro][c * 4]),
                      U + (gy0 + 1 + ro) * W + xbase + c * 4);
            } else {
                int li = l - NT - NU;
                int ro = li / 34, c = li - ro * 34;
                cpa16((uint32_t)__cvta_generic_to_shared(&sV[ro][c * 4]),
                      V + (gy0 + 1 + ro) * W + xbase + c * 4);
            }
        }
    } else {
        // Scalar clamped staging
        const int NT = ST_H * ST_W;                    // 2720
        const int NU = SU_H * ST_W;                    // 2448
        for (int l = tid; l < NT + 2 * NU; l += 512) {
            if (l < NT) {
                int ro = l / ST_W, sx = l - ro * ST_W;
                int py = min(max(gy0 + ro, 0), H - 1);
                int px = min(max(xbase + sx, 0), W - 1);
                sT[ro][sx] = __ldg(T + py * W + px);
            } else if (l < NT + NU) {
                int li = l - NT;
                int ro = li / ST_W, sx = li - ro * ST_W;
                int py = min(max(gy0 + 1 + ro, 0), H - 1);
                int px = min(max(xbase + sx, 0), W - 1);
                sU[ro][sx] = __ldg(U + py * W + px);
            } else {
                int li = l - NT - NU;
                int ro = li / ST_W, sx = li - ro * ST_W;
                int py = min(max(gy0 + 1 + ro, 0), H - 1);
                int px = min(max(xbase + sx, 0), W - 1);
                sV[ro][sx] = __ldg(V + py * W + px);
            }
        }
    }
    cpa_commit_wait();
    __syncthreads();

    const float dt = s_dt;
    const float rdx = 1.0f / DXF;

    // ---- stage 2: advect -> sM (pure smem) ----
    if (interior) {
        for (int l = tid; l < SM_H * SM_W; l += 512) {
            int my = l / SM_W, mx = l - my * SM_W;
            float c   = sT[my + 1][mx + 3];
            float lft = sT[my + 1][mx + 2];
            float rgt = sT[my + 1][mx + 4];
            float top = sT[my][mx + 3];
            float bot = sT[my + 2][mx + 3];
            float u = sU[my][mx + 3];
            float v = sV[my][mx + 3];
            float gx = (u > 0.0f) ? (c - lft) * rdx
                     : ((u < 0.0f) ? (rgt - c) * rdx : 0.0f);
            float gy = (v > 0.0f) ? (c - top) * rdx
                     : ((v < 0.0f) ? (bot - c) * rdx : 0.0f);
            sM[my][mx] = c + dt * (-u * gx - v * gy);
        }
    } else {
        for (int l = tid; l < SM_H * SM_W; l += 512) {
            int my = l / SM_W, mx = l - my * SM_W;
            int py = min(max(gy0 + 1 + my, 0), H - 1);
            int px = min(max(ox0 - 1 + mx, 0), W - 1);
            int sy = py - gy0;      // clamp center first, then offset slots
            int sx = px - xbase;    // (replicated slots hold edge values)
            float c   = sT[sy][sx];
            float lft = sT[sy][sx - 1];
            float rgt = sT[sy][sx + 1];
            float top = sT[sy - 1][sx];
            float bot = sT[sy + 1][sx];
            float u = sU[sy - 1][sx];
            float v = sV[sy - 1][sx];
            float gx = (u > 0.0f) ? (c - lft) * rdx
                     : ((u < 0.0f) ? (rgt - c) * rdx : 0.0f);
            float gy = (v > 0.0f) ? (c - top) * rdx
                     : ((v < 0.0f) ? (bot - c) * rdx : 0.0f);
            sM[my][mx] = c + dt * (-u * gx - v * gy);
        }
    }
    __syncthreads();

    // ---- stage 3: separable laplacian, register rotation ----
    {
        const float lapc = 0.25f * rdx * rdx;
        const float c4 = 4.0f * rdx * rdx;

        float a0 = sM[y0][tx3], a1 = sM[y0][tx3 + 1], a2 = sM[y0][tx3 + 2];
        float hb0 = a0 + 2.0f * a1 + a2;
        float b0 = sM[y0 + 1][tx3], b1 = sM[y0 + 1][tx3 + 1], b2 = sM[y0 + 1][tx3 + 2];
        float hb1 = b0 + 2.0f * b1 + b2;
        float cc = b1;

        size_t obase = (size_t)b * PLANE + (size_t)(oy0 + y0) * W + ox;

        #pragma unroll
        for (int r2 = 0; r2 < 4; ++r2) {
            int j = y0 + 2 + r2;
            float d0 = sM[j][tx3], d1 = sM[j][tx3 + 1], d2 = sM[j][tx3 + 2];
            float hb2 = d0 + 2.0f * d1 + d2;
            float lap = lapc * (hb0 + 2.0f * hb1 + hb2) - c4 * cc;
            out[obase] = cc + dt * (lap + Rpre[r2]);
            hb0 = hb1; hb1 = hb2; cc = d1;
            obase += W;
        }
    }

    // scalar dt — second output element
    if (bx == 0 && by == 0 && b == 0 && tid == 0 && out_size > BATCH * PLANE)
        out[BATCH * PLANE] = dt;
}

extern "C" void kernel_launch(void* const* d_in, const int* in_sizes, int n_in,
                              void* d_out, int out_size) {
    const float* in = (const float*)d_in[0];
    float* out = (float*)d_out;
    (void)in_sizes; (void)n_in;

    k_reduce<<<NRED, 512>>>(in);

    dim3 grd(W / TX, H / TY, BATCH);
    k_fused<<<grd, 512>>>(in, out, out_size);
}